// round 15
// baseline (speedup 1.0000x reference)
#include <cuda_runtime.h>
#include <cuda_fp16.h>
#include <cstdint>
#include <math.h>

// Problem constants
#define BB 4
#define TT 8192
#define HH 16
#define DD 64
#define CC 128                 // chunk length
#define NC (TT/CC)             // 64 chunks per sequence
#define BHN (BB*HH)            // 64 (b,h) pairs
#define NCHUNKS (BHN*NC)       // 4096 total chunks
#define EPSV 1e-6f

// Inter-CTA scan state: inclusive prefix of M^T (fp32, [e][d]) and z per chunk
__device__ float g_incl[(size_t)NCHUNKS * DD * DD];   // 64 MB
__device__ float g_zincl[(size_t)NCHUNKS * DD];       // 1 MB
__device__ int   g_flag[NCHUNKS];

__device__ __forceinline__ float phi_f(float x) {
    return x > 0.f ? x + 1.f : expf(x);   // elu(x)+1
}

__device__ __forceinline__ void mma16(float* d, const uint32_t* a, const uint32_t* b) {
    asm volatile(
        "mma.sync.aligned.m16n8k16.row.col.f32.f16.f16.f32 "
        "{%0,%1,%2,%3}, {%4,%5,%6,%7}, {%8,%9}, {%0,%1,%2,%3};"
        : "+f"(d[0]), "+f"(d[1]), "+f"(d[2]), "+f"(d[3])
        : "r"(a[0]), "r"(a[1]), "r"(a[2]), "r"(a[3]), "r"(b[0]), "r"(b[1]));
}

__device__ __forceinline__ uint32_t packh2(float lo, float hi) {
    __half2 h = __floats2half2_rn(lo, hi);
    return *(uint32_t*)&h;
}
__device__ __forceinline__ uint32_t sm32(const void* p) {
    return (uint32_t)__cvta_generic_to_shared(p);
}
__device__ __forceinline__ void ldsm4(uint32_t* r, uint32_t a) {
    asm volatile("ldmatrix.sync.aligned.m8n8.x4.shared.b16 {%0,%1,%2,%3}, [%4];"
                 : "=r"(r[0]), "=r"(r[1]), "=r"(r[2]), "=r"(r[3]) : "r"(a));
}
__device__ __forceinline__ void ldsm4t(uint32_t* r, uint32_t a) {
    asm volatile("ldmatrix.sync.aligned.m8n8.x4.trans.shared.b16 {%0,%1,%2,%3}, [%4];"
                 : "=r"(r[0]), "=r"(r[1]), "=r"(r[2]), "=r"(r[3]) : "r"(a));
}
__device__ __forceinline__ float2 ldcg2(const float* p) {
    float2 r;
    asm volatile("ld.global.cg.v2.f32 {%0,%1}, [%2];" : "=f"(r.x), "=f"(r.y) : "l"(p));
    return r;
}

// ---------------------------------------------------------------------------
// Reset kernel: zero flags (runs first each graph replay)
// ---------------------------------------------------------------------------
__global__ void k0_reset() {
    int i = blockIdx.x * 256 + threadIdx.x;
    if (i < NCHUNKS) g_flag[i] = 0;
}

// ---------------------------------------------------------------------------
// Fused kernel: grid = NCHUNKS, bid = chunk*BHN + bh  (chunk-major waves)
//  A: stage K(phi),V natural [t][d] fp16 (float4 LDG) + z partials
//  B: M^T_c[e][d] = sum_t V[t][e] phiK[t][d]  (accM in regs, k1 MMA block)
//  C: spin on predecessor flag (chunk-1, same bh)
//  D: read pred inclusive (fp32) -> sST fp16 (=S_prev^T) + sZ (=z_prev);
//     publish own inclusive (+M_c, +z_c); fence; flag
//  E: stage Q (phi) fp16
//  F: attention output (k3 compute block: Q@S, qz, QK/mask/A@V, epilogue)
// ---------------------------------------------------------------------------
#define S3 72

#define H_SK   0
#define H_SV   (H_SK + 128*S3)       // 9216
#define H_SQ   (H_SV + 128*S3)       // 18432
#define H_SST  (H_SQ + 128*S3)       // 27648
#define H_END  (H_SST + 64*S3)       // 32256 halfs = 64512 B
#define ZP_OFF 0                     // float idx after H_END: zpart[16*64]
#define SZ_OFF (ZP_OFF + 16*64)      // sZ[64]
#define SMEMF  (H_END*2 + (SZ_OFF + 64)*4 + 16)

__global__ void __launch_bounds__(256, 3) kfused(const float* __restrict__ qin,
                                                 const float* __restrict__ kin,
                                                 const float* __restrict__ vin,
                                                 float* __restrict__ out) {
    extern __shared__ __align__(16) char smraw[];
    __half* sK  = (__half*)smraw + H_SK;    // [128 t][72]  phiK
    __half* sV  = (__half*)smraw + H_SV;    // [128 t][72]  V (natural)
    __half* sQ  = (__half*)smraw + H_SQ;    // [128 t][72]  phiQ
    __half* sST = (__half*)smraw + H_SST;   // [64 e][72]   S_prev^T fp16
    float* sF   = (float*)((__half*)smraw + H_END);
    float* zpart = sF + ZP_OFF;             // [16][64]
    float* sZ = sF + SZ_OFF;                // [64] z_prev

    int bid = blockIdx.x;
    int cnk = bid >> 6, bh = bid & 63;      // chunk-major: pred = bid - BHN
    int b = bh >> 4, h = bh & 15;
    int t0 = cnk * CC;
    int tid = threadIdx.x;

    const size_t rowstride = (size_t)HH * DD;

    // ---- A: stage K (phi), V; z partials ----
    {
        int q4 = tid & 15, rg = tid >> 4;
        size_t base = ((size_t)b * TT + t0) * rowstride + (size_t)h * DD + q4 * 4;
        float z0 = 0.f, z1 = 0.f, z2 = 0.f, z3 = 0.f;
#pragma unroll 2
        for (int p = 0; p < 8; ++p) {
            int t = p * 16 + rg;
            size_t a = base + (size_t)t * rowstride;
            float4 kk = *(const float4*)(kin + a);
            float4 vv = *(const float4*)(vin + a);
            float p0 = phi_f(kk.x), p1 = phi_f(kk.y), p2 = phi_f(kk.z), p3 = phi_f(kk.w);
            z0 += p0; z1 += p1; z2 += p2; z3 += p3;
            __half* kd = sK + t * S3 + q4 * 4;
            *(uint32_t*)kd = packh2(p0, p1);
            *(uint32_t*)(kd + 2) = packh2(p2, p3);
            __half* vd = sV + t * S3 + q4 * 4;
            *(uint32_t*)vd = packh2(vv.x, vv.y);
            *(uint32_t*)(vd + 2) = packh2(vv.z, vv.w);
        }
        float* zr = zpart + rg * 64 + q4 * 4;
        zr[0] = z0; zr[1] = z1; zr[2] = z2; zr[3] = z3;
    }
    __syncthreads();

    int wid = tid >> 5, lane = tid & 31;
    int gid = lane >> 2, tig = lane & 3;
    int row8 = lane & 7, seg = lane >> 3;

    // ---- B: M^T MMAs (validated k1 block) ----
    float accM[4][4];
#pragma unroll
    for (int i = 0; i < 4; i++)
#pragma unroll
        for (int j = 0; j < 4; j++) accM[i][j] = 0.f;
    int m0 = (wid & 3) * 16;          // e-band (rows of M^T)
    int d0 = (wid >> 2) * 32;         // d-half (cols of M^T)
    {
        // A = V^T (m=e,k=t) from [t][e]: trans, m<-seg&1, k<-seg>>1
        uint32_t aVb = sm32(sV + (row8 + ((seg >> 1) << 3)) * S3 + m0 + ((seg & 1) << 3));
        // B = K^T (n=d,k=t) from [t][d]: trans, k<-seg&1, n<-seg>>1
        uint32_t bKb = sm32(sK + (row8 + ((seg & 1) << 3)) * S3 + d0 + ((seg >> 1) << 3));
#pragma unroll
        for (int ks = 0; ks < 8; ++ks) {
            uint32_t koff = (uint32_t)(16 * ks * S3) * 2;
            uint32_t a[4];
            ldsm4t(a, aVb + koff);
#pragma unroll
            for (int np = 0; np < 2; ++np) {
                uint32_t bf4[4];
                ldsm4t(bf4, bKb + koff + np * 32);
                mma16(accM[2 * np], a, bf4 + 0);
                mma16(accM[2 * np + 1], a, bf4 + 2);
            }
        }
    }

    // ---- C: spin on predecessor (chunk-1, same bh) ----
    if (cnk > 0 && tid == 0) {
        while (atomicAdd(&g_flag[bid - BHN], 0) == 0) __nanosleep(64);
    }
    __syncthreads();

    // ---- D: read pred inclusive -> sST/sZ; publish own inclusive; flag ----
    {
        float* inclMe = g_incl + (size_t)bid * 4096;
        const float* inclPr = g_incl + (size_t)(bid - BHN) * 4096;
#pragma unroll
        for (int nt = 0; nt < 4; ++nt) {
            int c0 = d0 + nt * 8 + 2 * tig;
            int r0 = m0 + gid;
            float2 plo = make_float2(0.f, 0.f), phv = make_float2(0.f, 0.f);
            if (cnk > 0) {
                plo = ldcg2(inclPr + (size_t)r0 * 64 + c0);
                phv = ldcg2(inclPr + (size_t)(r0 + 8) * 64 + c0);
            }
            *(uint32_t*)&sST[r0 * S3 + c0] = packh2(plo.x, plo.y);
            *(uint32_t*)&sST[(r0 + 8) * S3 + c0] = packh2(phv.x, phv.y);
            *(float2*)(inclMe + (size_t)r0 * 64 + c0) =
                make_float2(plo.x + accM[nt][0], plo.y + accM[nt][1]);
            *(float2*)(inclMe + (size_t)(r0 + 8) * 64 + c0) =
                make_float2(phv.x + accM[nt][2], phv.y + accM[nt][3]);
        }
        if (tid < 64) {
            float zc = 0.f;
#pragma unroll
            for (int r = 0; r < 16; ++r) zc += zpart[r * 64 + tid];
            float zp = (cnk > 0) ? __ldcg(g_zincl + (size_t)(bid - BHN) * 64 + tid) : 0.f;
            g_zincl[(size_t)bid * 64 + tid] = zp + zc;
            sZ[tid] = zp;
        }
    }
    __threadfence();
    __syncthreads();
    if (tid == 0) atomicExch(&g_flag[bid], 1);

    // ---- E: stage Q (phi) ----
    {
        int q4 = tid & 15, rg = tid >> 4;
        size_t base = ((size_t)b * TT + t0) * rowstride + (size_t)h * DD + q4 * 4;
#pragma unroll 2
        for (int p = 0; p < 8; ++p) {
            int t = p * 16 + rg;
            size_t a = base + (size_t)t * rowstride;
            float4 qq = *(const float4*)(qin + a);
            __half* qd = sQ + t * S3 + q4 * 4;
            *(uint32_t*)qd = packh2(phi_f(qq.x), phi_f(qq.y));
            *(uint32_t*)(qd + 2) = packh2(phi_f(qq.z), phi_f(qq.w));
        }
    }
    __syncthreads();

    // ---- F: attention output (validated k3 compute block) ----
    int bo = (wid < 4) ? wid : (11 - wid);   // SMSP-balanced band assignment
    int r_lo = bo * 16 + gid, r_hi = r_lo + 8;

    // LDSM bases
    uint32_t aQb = sm32(sQ + (bo * 16 + row8 + ((seg & 1) << 3)) * S3 + ((seg & 2) << 2));
    uint32_t sTb = sm32(sST + (row8 + ((seg >> 1) << 3)) * S3 + ((seg & 1) << 3));
    uint32_t sKb = sm32(sK + (row8 + ((seg >> 1) << 3)) * S3 + ((seg & 1) << 3));
    uint32_t sVb = sm32(sV + (row8 + ((seg & 1) << 3)) * S3 + ((seg >> 1) << 3));

    uint32_t afr[4][4];
#pragma unroll
    for (int ks = 0; ks < 4; ++ks) ldsm4(afr[ks], aQb + ks * 32);

    float acc[8][4];
#pragma unroll
    for (int i = 0; i < 8; i++)
#pragma unroll
        for (int j = 0; j < 4; j++) acc[i][j] = 0.f;

    // phase 1: acc = phiQ @ S_prev
#pragma unroll
    for (int ks = 0; ks < 4; ++ks) {
#pragma unroll
        for (int ntp = 0; ntp < 4; ++ntp) {
            uint32_t bf4[4];
            ldsm4(bf4, sTb + (uint32_t)(16 * ntp * S3) * 2 + ks * 32);
            mma16(acc[2 * ntp], afr[ks], bf4 + 0);
            mma16(acc[2 * ntp + 1], afr[ks], bf4 + 2);
        }
    }

    // phase 2: qz = phiQ . z_prev
    float qlo = 0.f, qhi = 0.f;
#pragma unroll
    for (int dd = 0; dd < 16; ++dd) {
        int d2 = tig * 16 + dd;
        float zv = sZ[d2];
        qlo += __half2float(sQ[r_lo * S3 + d2]) * zv;
        qhi += __half2float(sQ[r_hi * S3 + d2]) * zv;
    }
    qlo += __shfl_xor_sync(0xffffffffu, qlo, 1);
    qlo += __shfl_xor_sync(0xffffffffu, qlo, 2);
    qhi += __shfl_xor_sync(0xffffffffu, qhi, 1);
    qhi += __shfl_xor_sync(0xffffffffu, qhi, 2);

    // phase 3: per 16-col k-tile: QK -> mask -> pack -> A@V
    float rs_lo = 0.f, rs_hi = 0.f;
#pragma unroll 2
    for (int j = 0; j <= bo; ++j) {
        float acc8[2][4];
#pragma unroll
        for (int u = 0; u < 2; ++u)
#pragma unroll
            for (int i = 0; i < 4; ++i) acc8[u][i] = 0.f;

        uint32_t jkoff = (uint32_t)(16 * j * S3) * 2;
#pragma unroll
        for (int ks = 0; ks < 4; ++ks) {
            uint32_t bf4[4];
            ldsm4(bf4, sKb + jkoff + ks * 32);
            mma16(acc8[0], afr[ks], bf4 + 0);
            mma16(acc8[1], afr[ks], bf4 + 2);
        }

        int cb0 = 16 * j + 2 * tig;
        int cb1 = cb0 + 8;
        float A00 = (cb0     <= r_lo) ? acc8[0][0] : 0.f;
        float A01 = (cb0 + 1 <= r_lo) ? acc8[0][1] : 0.f;
        float A02 = (cb0     <= r_hi) ? acc8[0][2] : 0.f;
        float A03 = (cb0 + 1 <= r_hi) ? acc8[0][3] : 0.f;
        float A10 = (cb1     <= r_lo) ? acc8[1][0] : 0.f;
        float A11 = (cb1 + 1 <= r_lo) ? acc8[1][1] : 0.f;
        float A12 = (cb1     <= r_hi) ? acc8[1][2] : 0.f;
        float A13 = (cb1 + 1 <= r_hi) ? acc8[1][3] : 0.f;
        rs_lo += A00 + A01 + A10 + A11;
        rs_hi += A02 + A03 + A12 + A13;
        uint32_t aA[4];
        aA[0] = packh2(A00, A01);
        aA[1] = packh2(A02, A03);
        aA[2] = packh2(A10, A11);
        aA[3] = packh2(A12, A13);

#pragma unroll
        for (int ntp = 0; ntp < 4; ++ntp) {
            uint32_t bf4[4];
            ldsm4t(bf4, sVb + jkoff + (uint32_t)(16 * ntp) * 2);
            mma16(acc[2 * ntp], aA, bf4 + 0);
            mma16(acc[2 * ntp + 1], aA, bf4 + 2);
        }
    }

    rs_lo += __shfl_xor_sync(0xffffffffu, rs_lo, 1);
    rs_lo += __shfl_xor_sync(0xffffffffu, rs_lo, 2);
    rs_hi += __shfl_xor_sync(0xffffffffu, rs_hi, 1);
    rs_hi += __shfl_xor_sync(0xffffffffu, rs_hi, 2);

    // epilogue
    float inv_lo = 1.f / (rs_lo + qlo + EPSV);
    float inv_hi = 1.f / (rs_hi + qhi + EPSV);
    size_t obase = ((size_t)b * TT + t0) * rowstride + (size_t)h * DD;
#pragma unroll
    for (int nt = 0; nt < 8; ++nt) {
        int c0 = nt * 8 + 2 * tig;
        *(float2*)(out + obase + (size_t)r_lo * rowstride + c0) =
            make_float2(acc[nt][0] * inv_lo, acc[nt][1] * inv_lo);
        *(float2*)(out + obase + (size_t)r_hi * rowstride + c0) =
            make_float2(acc[nt][2] * inv_hi, acc[nt][3] * inv_hi);
    }
}

// ---------------------------------------------------------------------------
extern "C" void kernel_launch(void* const* d_in, const int* in_sizes, int n_in,
                              void* d_out, int out_size) {
    const float* q = (const float*)d_in[0];
    const float* k = (const float*)d_in[1];
    const float* v = (const float*)d_in[2];
    float* out = (float*)d_out;

    cudaFuncSetAttribute(kfused, cudaFuncAttributeMaxDynamicSharedMemorySize, SMEMF);

    k0_reset<<<16, 256>>>();
    kfused<<<NCHUNKS, 256, SMEMF>>>(q, k, v, out);
}

// round 16
// speedup vs baseline: 1.0812x; 1.0812x over previous
#include <cuda_runtime.h>
#include <cuda_fp16.h>
#include <cstdint>
#include <math.h>

// Problem constants
#define BB 4
#define TT 8192
#define HH 16
#define DD 64
#define CC 128                 // chunk length
#define NC (TT/CC)             // 64 chunks per sequence
#define BHN (BB*HH)            // 64 (b,h) pairs
#define NCHUNKS (BHN*NC)       // 4096 total chunks
#define EPSV 1e-6f

// Scratch (fp16): per-chunk M^T (e-major), converted in-place to exclusive prefix S_prev^T
__device__ __half g_M16[(size_t)NCHUNKS * DD * DD];   // 32 MB
__device__ float  g_z[(size_t)NCHUNKS * DD];          // 1 MB (fp32)

__device__ __forceinline__ float phi_f(float x) {
    return x > 0.f ? x + 1.f : expf(x);   // elu(x)+1
}

__device__ __forceinline__ void mma16(float* d, const uint32_t* a, const uint32_t* b) {
    asm volatile(
        "mma.sync.aligned.m16n8k16.row.col.f32.f16.f16.f32 "
        "{%0,%1,%2,%3}, {%4,%5,%6,%7}, {%8,%9}, {%0,%1,%2,%3};"
        : "+f"(d[0]), "+f"(d[1]), "+f"(d[2]), "+f"(d[3])
        : "r"(a[0]), "r"(a[1]), "r"(a[2]), "r"(a[3]), "r"(b[0]), "r"(b[1]));
}

__device__ __forceinline__ uint32_t packh2(float lo, float hi) {
    __half2 h = __floats2half2_rn(lo, hi);
    return *(uint32_t*)&h;
}
__device__ __forceinline__ uint32_t sm32(const void* p) {
    return (uint32_t)__cvta_generic_to_shared(p);
}
__device__ __forceinline__ void ldsm4(uint32_t* r, uint32_t a) {
    asm volatile("ldmatrix.sync.aligned.m8n8.x4.shared.b16 {%0,%1,%2,%3}, [%4];"
                 : "=r"(r[0]), "=r"(r[1]), "=r"(r[2]), "=r"(r[3]) : "r"(a));
}
__device__ __forceinline__ void ldsm4t(uint32_t* r, uint32_t a) {
    asm volatile("ldmatrix.sync.aligned.m8n8.x4.trans.shared.b16 {%0,%1,%2,%3}, [%4];"
                 : "=r"(r[0]), "=r"(r[1]), "=r"(r[2]), "=r"(r[3]) : "r"(a));
}
__device__ __forceinline__ void cpasync16(uint32_t smem_dst, const void* gsrc) {
    asm volatile("cp.async.ca.shared.global [%0], [%1], 16;" :: "r"(smem_dst), "l"(gsrc));
}

// ---------------------------------------------------------------------------
// Kernel 1 (R14 config): per-chunk M^T[e][d] = sum_t V[t][e] phiK[t][d],
// z_c = sum_t phiK.  Natural row-major staging via float4; ldsm.trans operands.
// grid = NCHUNKS, block = 256.
// ---------------------------------------------------------------------------
#define S1 72     // 144B row stride: /16 ok, 36 words == 4 mod 32 -> conflict-free
#define SMEM1 (2*128*S1*2 + 16*64*4 + 16)

__global__ void __launch_bounds__(256, 4) k1_kv(const float* __restrict__ kin,
                                                const float* __restrict__ vin) {
    extern __shared__ __align__(16) char smraw[];
    __half* sK1 = (__half*)smraw;              // [128 t][72] phiK
    __half* sV1 = sK1 + 128 * S1;              // [128 t][72] V
    float* sZp = (float*)(sV1 + 128 * S1);     // [16][64] z partials

    int g = blockIdx.x;
    int bh = g >> 6, c = g & 63;
    int b = bh >> 4, h = bh & 15;
    int t0 = c * CC;
    int tid = threadIdx.x;
    int q4 = tid & 15, rg = tid >> 4;          // col-quad, row group

    const size_t rowstride = (size_t)HH * DD;
    size_t base = ((size_t)b * TT + t0) * rowstride + (size_t)h * DD + q4 * 4;

    float z0 = 0.f, z1 = 0.f, z2 = 0.f, z3 = 0.f;
#pragma unroll 2
    for (int p = 0; p < 8; ++p) {
        int t = p * 16 + rg;
        size_t a = base + (size_t)t * rowstride;
        float4 kk = *(const float4*)(kin + a);
        float4 vv = *(const float4*)(vin + a);
        float p0 = phi_f(kk.x), p1 = phi_f(kk.y), p2 = phi_f(kk.z), p3 = phi_f(kk.w);
        z0 += p0; z1 += p1; z2 += p2; z3 += p3;
        __half* kd = sK1 + t * S1 + q4 * 4;
        *(uint32_t*)kd = packh2(p0, p1);
        *(uint32_t*)(kd + 2) = packh2(p2, p3);
        __half* vd = sV1 + t * S1 + q4 * 4;
        *(uint32_t*)vd = packh2(vv.x, vv.y);
        *(uint32_t*)(vd + 2) = packh2(vv.z, vv.w);
    }
    {
        float* zr = sZp + rg * 64 + q4 * 4;
        zr[0] = z0; zr[1] = z1; zr[2] = z2; zr[3] = z3;
    }
    __syncthreads();
    if (tid < 64) {
        float s = 0.f;
#pragma unroll
        for (int r = 0; r < 16; ++r) s += sZp[r * 64 + tid];
        g_z[(size_t)g * 64 + tid] = s;
    }

    int w = tid >> 5, lane = tid & 31;
    int gid = lane >> 2, tig = lane & 3;
    int row8 = lane & 7, seg = lane >> 3;
    int m0 = (w & 3) * 16;          // e-band (rows of M^T)
    int d0 = (w >> 2) * 32;         // d-half (cols of M^T)

    // A = V^T (m=e,k=t) from [t][e] storage: trans, m<-seg&1, k<-seg>>1
    uint32_t aVb = sm32(sV1 + (row8 + ((seg >> 1) << 3)) * S1 + m0 + ((seg & 1) << 3));
    // B = K^T (n=d,k=t) from [t][d] storage: trans, k<-seg&1, n<-seg>>1
    uint32_t bKb = sm32(sK1 + (row8 + ((seg & 1) << 3)) * S1 + d0 + ((seg >> 1) << 3));

    float acc[4][4];
#pragma unroll
    for (int i = 0; i < 4; i++)
#pragma unroll
        for (int j = 0; j < 4; j++) acc[i][j] = 0.f;

#pragma unroll
    for (int ks = 0; ks < 8; ++ks) {
        uint32_t koff = (uint32_t)(16 * ks * S1) * 2;
        uint32_t a[4];
        ldsm4t(a, aVb + koff);
#pragma unroll
        for (int np = 0; np < 2; ++np) {
            uint32_t bf4[4];
            ldsm4t(bf4, bKb + koff + np * 32);
            mma16(acc[2 * np], a, bf4 + 0);
            mma16(acc[2 * np + 1], a, bf4 + 2);
        }
    }

    __half* Mout = g_M16 + (size_t)g * DD * DD;   // [e][d]
#pragma unroll
    for (int nt = 0; nt < 4; ++nt) {
        int c0 = d0 + nt * 8 + 2 * tig;
        int r0 = m0 + gid;
        *(uint32_t*)(Mout + (size_t)r0 * DD + c0) = packh2(acc[nt][0], acc[nt][1]);
        *(uint32_t*)(Mout + (size_t)(r0 + 8) * DD + c0) = packh2(acc[nt][2], acc[nt][3]);
    }
}

// ---------------------------------------------------------------------------
// Kernel 2: exclusive prefix over chunks (fp16 data, fp32 running sums).
// uint2 per thread (8B loads), two 32-chunk half-passes to bound registers.
// grid = BHN*4, block = 256.
// ---------------------------------------------------------------------------
__global__ void __launch_bounds__(256) k2_scan() {
    int bh = blockIdx.x >> 2;
    int seg = blockIdx.x & 3;
    int u = seg * 256 + threadIdx.x;               // uint2 index, 1024 per chunk
    uint2* base = (uint2*)g_M16 + (size_t)bh * 64 * 1024 + u;

    float r0 = 0.f, r1 = 0.f, r2 = 0.f, r3 = 0.f;
#pragma unroll
    for (int hf = 0; hf < 2; ++hf) {
        uint2 vals[32];
#pragma unroll
        for (int c = 0; c < 32; ++c) vals[c] = base[(size_t)(hf * 32 + c) * 1024];
#pragma unroll
        for (int c = 0; c < 32; ++c) {
            __half2 h0 = *(__half2*)&vals[c].x;
            __half2 h1 = *(__half2*)&vals[c].y;
            float a0 = __low2float(h0), a1 = __high2float(h0);
            float a2 = __low2float(h1), a3 = __high2float(h1);
            vals[c].x = packh2(r0, r1);
            vals[c].y = packh2(r2, r3);
            r0 += a0; r1 += a1; r2 += a2; r3 += a3;
        }
#pragma unroll
        for (int c = 0; c < 32; ++c) base[(size_t)(hf * 32 + c) * 1024] = vals[c];
    }
}

__global__ void __launch_bounds__(64) k2_scanz() {
    int bh = blockIdx.x;
    size_t base = (size_t)bh * 64 * 64 + threadIdx.x;

    float vals[64];
#pragma unroll
    for (int c = 0; c < 64; ++c) vals[c] = g_z[base + (size_t)c * 64];
    float run = 0.f;
#pragma unroll
    for (int c = 0; c < 64; ++c) {
        float t = vals[c];
        vals[c] = run;
        run += t;
    }
#pragma unroll
    for (int c = 0; c < 64; ++c) g_z[base + (size_t)c * 64] = vals[c];
}

// ---------------------------------------------------------------------------
// Kernel 3 (R12 config + cp.async S-copy): 256 threads, 8 warps, warp owns
// band bo = wid<4 ? wid : 11-wid.  Q a-fragments hoisted via ldmatrix.x4;
// V stored transposed [e][t]; S_prev^T fetched with cp.async under staging.
// ---------------------------------------------------------------------------
#define SQS 72    // 144B stride: 16 mod 128 -> LDSM conflict-free, 16B aligned rows
#define SVS 136   // 272B stride: 16 mod 128
#define SSS 72

#define H_SQ   0
#define H_SK   (H_SQ + 128*SQS)      // 9216
#define H_SVT  (H_SK + 128*SQS)      // 18432
#define H_SST  (H_SVT + 64*SVS)      // 27136
#define H_END  (H_SST + 64*SSS)      // 31744 halfs
#define SMEM3  (H_END*2 + 64*4 + 16)

__global__ void __launch_bounds__(256, 3) k3_out(const float* __restrict__ qin,
                                                 const float* __restrict__ kin,
                                                 const float* __restrict__ vin,
                                                 float* __restrict__ out) {
    extern __shared__ __align__(16) char smraw[];
    __half* sQ  = (__half*)smraw + H_SQ;    // [128 t][72]  phiQ
    __half* sK  = (__half*)smraw + H_SK;    // [128 s][72]  phiK
    __half* sVT = (__half*)smraw + H_SVT;   // [64 e][136]  V^T (e rows, t cols)
    __half* sST = (__half*)smraw + H_SST;   // [64 e][72]   S_prev^T
    float* sZ = (float*)((__half*)smraw + H_END);  // [64]

    int g = blockIdx.x;
    int bh = g >> 6, c = g & 63;
    int b = bh >> 4, h = bh & 15;
    int t0 = c * CC;
    int tid = threadIdx.x;

    const size_t rowstride = (size_t)HH * DD;

    // ---- S_prev^T via cp.async first: latency hides under staging below ----
    {
        const __half* Sp = g_M16 + (size_t)g * 4096;
#pragma unroll
        for (int i = tid; i < 512; i += 256) {
            int e = i >> 3, dh = (i & 7) * 8;
            cpasync16(sm32(&sST[e * SSS + dh]), Sp + i * 8);
        }
        asm volatile("cp.async.commit_group;" ::: "memory");
    }

    // ---- load phase (R12 pattern: scalar LDG, deep unroll) ----
    {
        int d = tid & 63, rg = tid >> 6;
        size_t base = ((size_t)b * TT + t0) * rowstride + (size_t)h * DD + d;
#pragma unroll 8
        for (int p = 0; p < 32; ++p) {
            int t = p * 4 + rg;
            size_t a = base + (size_t)t * rowstride;
            sQ[t * SQS + d] = __float2half_rn(phi_f(qin[a]));
            sK[t * SQS + d] = __float2half_rn(phi_f(kin[a]));
            sVT[d * SVS + t] = __float2half_rn(vin[a]);
        }
        if (tid < 64) sZ[tid] = g_z[(size_t)g * 64 + tid];
    }
    asm volatile("cp.async.wait_group 0;" ::: "memory");
    __syncthreads();

    int wid = tid >> 5, lane = tid & 31;
    int gid = lane >> 2, tig = lane & 3;
    int row8 = lane & 7, seg = lane >> 3;
    int bo = (wid < 4) ? wid : (11 - wid);   // SMSP-balanced band assignment
    int r_lo = bo * 16 + gid, r_hi = r_lo + 8;

    // LDSM per-thread base addresses
    // A matrices: (seg&1)->rows+8, (seg&2)->k+8
    uint32_t aQbase = sm32(sQ + (bo * 16 + row8 + ((seg & 1) << 3)) * SQS + ((seg & 2) << 2));
    // B matrices: (seg&1)->k+8, (seg>>1)->n+8
    uint32_t sTbase = sm32(sST + (row8 + ((seg >> 1) << 3)) * SSS + ((seg & 1) << 3));
    uint32_t sKbase = sm32(sK + (row8 + ((seg >> 1) << 3)) * SQS + ((seg & 1) << 3));
    uint32_t sVbase = sm32(sVT + (row8 + ((seg >> 1) << 3)) * SVS + ((seg & 1) << 3));

    // ---- Q a-fragments: loaded once, reused by Q@S and all QK tiles ----
    uint32_t afr[4][4];
#pragma unroll
    for (int ks = 0; ks < 4; ++ks) ldsm4(afr[ks], aQbase + ks * 32);

    float acc[8][4];
#pragma unroll
    for (int i = 0; i < 8; i++)
#pragma unroll
        for (int j = 0; j < 4; j++) acc[i][j] = 0.f;

    // ---- phase 1: acc = phiQ @ S_prev ----
#pragma unroll
    for (int ks = 0; ks < 4; ++ks) {
#pragma unroll
        for (int ntp = 0; ntp < 4; ++ntp) {
            uint32_t bf4[4];
            ldsm4(bf4, sTbase + (uint32_t)(16 * ntp * SSS) * 2 + ks * 32);
            mma16(acc[2 * ntp], afr[ks], bf4 + 0);
            mma16(acc[2 * ntp + 1], afr[ks], bf4 + 2);
        }
    }

    // ---- phase 2: qz = phiQ . z_prev ----
    float qlo = 0.f, qhi = 0.f;
#pragma unroll
    for (int dd = 0; dd < 16; ++dd) {
        int d2 = tig * 16 + dd;
        float zv = sZ[d2];
        qlo += __half2float(sQ[r_lo * SQS + d2]) * zv;
        qhi += __half2float(sQ[r_hi * SQS + d2]) * zv;
    }
    qlo += __shfl_xor_sync(0xffffffffu, qlo, 1);
    qlo += __shfl_xor_sync(0xffffffffu, qlo, 2);
    qhi += __shfl_xor_sync(0xffffffffu, qhi, 1);
    qhi += __shfl_xor_sync(0xffffffffu, qhi, 2);

    // ---- phase 3: per 16-col k-tile: QK -> mask -> pack -> A@V ----
    float rs_lo = 0.f, rs_hi = 0.f;
#pragma unroll 2
    for (int j = 0; j <= bo; ++j) {
        float acc8[2][4];
#pragma unroll
        for (int u = 0; u < 2; ++u)
#pragma unroll
            for (int i = 0; i < 4; ++i) acc8[u][i] = 0.f;

        uint32_t jkoff = (uint32_t)(16 * j * SQS) * 2;
#pragma unroll
        for (int ks = 0; ks < 4; ++ks) {
            uint32_t bf4[4];
            ldsm4(bf4, sKbase + jkoff + ks * 32);
            mma16(acc8[0], afr[ks], bf4 + 0);
            mma16(acc8[1], afr[ks], bf4 + 2);
        }

        // mask (col <= row), rowsum, pack acc -> a-fragment (layout-exact)
        int cb0 = 16 * j + 2 * tig;
        int cb1 = cb0 + 8;
        float A00 = (cb0     <= r_lo) ? acc8[0][0] : 0.f;
        float A01 = (cb0 + 1 <= r_lo) ? acc8[0][1] : 0.f;
        float A02 = (cb0     <= r_hi) ? acc8[0][2] : 0.f;
        float A03 = (cb0 + 1 <= r_hi) ? acc8[0][3] : 0.f;
        float A10 = (cb1     <= r_lo) ? acc8[1][0] : 0.f;
        float A11 = (cb1 + 1 <= r_lo) ? acc8[1][1] : 0.f;
        float A12 = (cb1     <= r_hi) ? acc8[1][2] : 0.f;
        float A13 = (cb1 + 1 <= r_hi) ? acc8[1][3] : 0.f;
        rs_lo += A00 + A01 + A10 + A11;
        rs_hi += A02 + A03 + A12 + A13;
        uint32_t aA[4];
        aA[0] = packh2(A00, A01);
        aA[1] = packh2(A02, A03);
        aA[2] = packh2(A10, A11);
        aA[3] = packh2(A12, A13);

        // A@V: k16-range = s in [16j, 16j+16)
        uint32_t jvoff = (uint32_t)(16 * j) * 2;
#pragma unroll
        for (int ntp = 0; ntp < 4; ++ntp) {
            uint32_t bf4[4];
            ldsm4(bf4, sVbase + (uint32_t)(16 * ntp * SVS) * 2 + jvoff);
            mma16(acc[2 * ntp], aA, bf4 + 0);
            mma16(acc[2 * ntp + 1], aA, bf4 + 2);
        }
    }

    rs_lo += __shfl_xor_sync(0xffffffffu, rs_lo, 1);
    rs_lo += __shfl_xor_sync(0xffffffffu, rs_lo, 2);
    rs_hi += __shfl_xor_sync(0xffffffffu, rs_hi, 1);
    rs_hi += __shfl_xor_sync(0xffffffffu, rs_hi, 2);

    // ---- epilogue ----
    float inv_lo = 1.f / (rs_lo + qlo + EPSV);
    float inv_hi = 1.f / (rs_hi + qhi + EPSV);
    size_t obase = ((size_t)b * TT + t0) * rowstride + (size_t)h * DD;
#pragma unroll
    for (int nt = 0; nt < 8; ++nt) {
        int c0 = nt * 8 + 2 * tig;
        *(float2*)(out + obase + (size_t)r_lo * rowstride + c0) =
            make_float2(acc[nt][0] * inv_lo, acc[nt][1] * inv_lo);
        *(float2*)(out + obase + (size_t)r_hi * rowstride + c0) =
            make_float2(acc[nt][2] * inv_hi, acc[nt][3] * inv_hi);
    }
}

// ---------------------------------------------------------------------------
extern "C" void kernel_launch(void* const* d_in, const int* in_sizes, int n_in,
                              void* d_out, int out_size) {
    const float* q = (const float*)d_in[0];
    const float* k = (const float*)d_in[1];
    const float* v = (const float*)d_in[2];
    float* out = (float*)d_out;

    cudaFuncSetAttribute(k1_kv, cudaFuncAttributeMaxDynamicSharedMemorySize, SMEM1);
    cudaFuncSetAttribute(k3_out, cudaFuncAttributeMaxDynamicSharedMemorySize, SMEM3);

    k1_kv<<<NCHUNKS, 256, SMEM1>>>(k, v);
    k2_scan<<<BHN * 4, 256>>>();
    k2_scanz<<<BHN, 64>>>();
    k3_out<<<NCHUNKS, 256, SMEM3>>>(q, k, v, out);
}